// round 9
// baseline (speedup 1.0000x reference)
#include <cuda_runtime.h>
#include <cuda_fp16.h>
#include <math.h>
#include <stdint.h>

#define B_SZ  2
#define S_LEN 2048
#define D_DIM 1024
#define H_NUM 16
#define DKH   64
#define MTOT  (B_SZ * S_LEN)          // 4096

// ---------------------------------------------------------------------------
// Scratch (allocation-free rule: __device__ globals). fp16 operands.
// ---------------------------------------------------------------------------
__device__ __half g_Qh[MTOT * D_DIM], g_Ql[MTOT * D_DIM];    // Q proj (split)
__device__ __half g_Kv[MTOT * D_DIM];                        // K proj (single)
__device__ __half g_Vv[MTOT * D_DIM];                        // V proj (single)
__device__ __half g_Xh[MTOT * D_DIM], g_Xl[MTOT * D_DIM];    // attn out (split)

// ===========================================================================
// helpers
// ===========================================================================
__device__ __forceinline__ uint32_t smem_u32(const void* p) {
    uint32_t a;
    asm("{ .reg .u64 t; cvta.to.shared.u64 t, %1; cvt.u32.u64 %0, t; }"
        : "=r"(a) : "l"(p));
    return a;
}
__device__ __forceinline__ void ldmx4(uint32_t* r, uint32_t addr) {
    asm volatile("ldmatrix.sync.aligned.m8n8.x4.shared.b16 {%0,%1,%2,%3}, [%4];"
                 : "=r"(r[0]), "=r"(r[1]), "=r"(r[2]), "=r"(r[3]) : "r"(addr));
}
__device__ __forceinline__ void ldmx4t(uint32_t* r, uint32_t addr) {
    asm volatile("ldmatrix.sync.aligned.m8n8.x4.trans.shared.b16 {%0,%1,%2,%3}, [%4];"
                 : "=r"(r[0]), "=r"(r[1]), "=r"(r[2]), "=r"(r[3]) : "r"(addr));
}
__device__ __forceinline__ void mma16816(float* c, const uint32_t* a,
                                         uint32_t b0, uint32_t b1) {
    asm volatile(
        "mma.sync.aligned.m16n8k16.row.col.f32.f16.f16.f32 "
        "{%0,%1,%2,%3}, {%4,%5,%6,%7}, {%8,%9}, {%0,%1,%2,%3};"
        : "+f"(c[0]), "+f"(c[1]), "+f"(c[2]), "+f"(c[3])
        : "r"(a[0]), "r"(a[1]), "r"(a[2]), "r"(a[3]), "r"(b0), "r"(b1));
}
__device__ __forceinline__ uint32_t packh(float x, float y) {
    __half2 h = __float22half2_rn(make_float2(x, y));
    return *(uint32_t*)&h;
}
__device__ __forceinline__ void split2h(float x, float y, uint32_t& h, uint32_t& l) {
    h = packh(x, y);
    __half2 t = *(__half2*)&h;
    float2 f = __half22float2(t);
    l = packh(x - f.x, y - f.y);
}
__device__ __forceinline__ void cpasync16(uint32_t dst, const void* src) {
    asm volatile("cp.async.cg.shared.global [%0], [%1], 16;"
                 :: "r"(dst), "l"(src));
}
__device__ __forceinline__ void cp_commit() {
    asm volatile("cp.async.commit_group;" ::: "memory");
}
__device__ __forceinline__ void cp_wait0() {
    asm volatile("cp.async.wait_group 0;" ::: "memory");
}
__device__ __forceinline__ void cp_wait1() {
    asm volatile("cp.async.wait_group 1;" ::: "memory");
}

// ===========================================================================
// Shared GEMM geometry (512 threads, 16 warps = 4 m x 4 n, warp tile 32x32)
// ===========================================================================
constexpr int SASB    = 144;               // padded row bytes (64 fp16 + pad)
constexpr int GT      = 128 * SASB;        // 18432 per 128-row tile
constexpr int GSTAGE  = 3 * GT;            // 55296 per stage (Ahi,Alo,B)
constexpr int SM_GEMM_TOTAL = 2 * GSTAGE;  // 110592
constexpr int STAGES  = D_DIM / 64;        // 16

__device__ __forceinline__ void gemm_stage_compute(
    uint32_t bufb, int warp_m, int warp_n, int lr, int lkb, float acc[2][4][4])
{
#pragma unroll
    for (int ks = 0; ks < 4; ks++) {
        const uint32_t kb = ks * 32 + lkb;
        uint32_t ah[2][4], al[2][4];
#pragma unroll
        for (int mi = 0; mi < 2; mi++) {
            const uint32_t byte = (warp_m * 32 + mi * 16 + lr) * SASB + kb;
            ldmx4(ah[mi], bufb + byte);
            ldmx4(al[mi], bufb + GT + byte);
        }
        uint32_t bh[4][2];
#pragma unroll
        for (int nb = 0; nb < 2; nb++) {
            const uint32_t byte = (warp_n * 32 + nb * 16 + lr) * SASB + kb;
            uint32_t r[4];
            ldmx4(r, bufb + 2 * GT + byte);
            bh[nb * 2][0] = r[0]; bh[nb * 2 + 1][0] = r[1];
            bh[nb * 2][1] = r[2]; bh[nb * 2 + 1][1] = r[3];
        }
#pragma unroll
        for (int mi = 0; mi < 2; mi++)
#pragma unroll
            for (int ni = 0; ni < 4; ni++) {
                mma16816(acc[mi][ni], ah[mi], bh[ni][0], bh[ni][1]);
                mma16816(acc[mi][ni], al[mi], bh[ni][0], bh[ni][1]);
            }
    }
}

// ===========================================================================
// gemm_proj: z=0: Q (split out), z=1: K (single), z=2: V (single).
// f32 inputs; producer converts/splits to fp16 smem in-kernel.
// ===========================================================================
__global__ __launch_bounds__(512, 1)
void gemm_proj(const float* __restrict__ Aq, const float* __restrict__ Ak,
               const float* __restrict__ Av,
               const float* __restrict__ Wq, const float* __restrict__ Wk,
               const float* __restrict__ Wv,
               __half* __restrict__ Qh, __half* __restrict__ Ql,
               __half* __restrict__ Kv, __half* __restrict__ Vv)
{
    extern __shared__ char smc[];
    const uint32_t sb = smem_u32(smc);
    const int tid  = threadIdx.x;
    const int wid  = tid >> 5;
    const int lane = tid & 31;
    const int warp_m = wid & 3;
    const int warp_n = wid >> 2;
    const int m0 = blockIdx.y * 128;
    const int n0 = blockIdx.x * 128;
    const int z  = blockIdx.z;
    const int K  = D_DIM, N = D_DIM;

    const float* A = (z == 0) ? Aq : (z == 1) ? Ak : Av;
    const float* W = (z == 0) ? Wq : (z == 1) ? Wk : Wv;
    const float* Abase = A + (size_t)m0 * K;
    const float* Wbase = W + (size_t)n0 * K;

    float acc[2][4][4];
#pragma unroll
    for (int mi = 0; mi < 2; mi++)
#pragma unroll
        for (int ni = 0; ni < 4; ni++)
#pragma unroll
            for (int q = 0; q < 4; q++) acc[mi][ni][q] = 0.f;

    const int lr  = lane & 15;
    const int lkb = (lane >> 4) << 4;

    float4 pa[4], pw[4];
    auto load_regs = [&](int s) {
#pragma unroll
        for (int i = 0; i < 4; i++) {
            const int c = i * 512 + tid;          // 0..2047
            const int row = c >> 4, ch = c & 15;
            pa[i] = *(const float4*)(Abase + (size_t)row * K + s * 64 + ch * 4);
            pw[i] = *(const float4*)(Wbase + (size_t)row * K + s * 64 + ch * 4);
        }
    };
    auto store_regs = [&](uint32_t bufo) {
        char* hi_p = smc + bufo;
        char* lo_p = smc + bufo + GT;
        char* b_p  = smc + bufo + 2 * GT;
#pragma unroll
        for (int i = 0; i < 4; i++) {
            const int c = i * 512 + tid;
            const int row = c >> 4, ch = c & 15;
            const uint32_t off = row * SASB + ch * 8;
            uint32_t h0, l0, h1, l1;
            split2h(pa[i].x, pa[i].y, h0, l0);
            split2h(pa[i].z, pa[i].w, h1, l1);
            *(uint2*)(hi_p + off) = make_uint2(h0, h1);
            *(uint2*)(lo_p + off) = make_uint2(l0, l1);
            *(uint2*)(b_p + off)  = make_uint2(packh(pw[i].x, pw[i].y),
                                               packh(pw[i].z, pw[i].w));
        }
    };

    load_regs(0);
    store_regs(0);
    __syncthreads();

    for (int s = 0; s < STAGES; s++) {
        if (s + 1 < STAGES) load_regs(s + 1);
        gemm_stage_compute(sb + (s & 1) * GSTAGE, warp_m, warp_n, lr, lkb, acc);
        if (s + 1 < STAGES) store_regs(((s + 1) & 1) * GSTAGE);
        __syncthreads();
    }

    // ---- epilogue ----
    const int er = lane >> 2;
    const int ec = (lane & 3) * 2;
    if (z == 0) {
#pragma unroll
        for (int mi = 0; mi < 2; mi++)
#pragma unroll
            for (int ni = 0; ni < 4; ni++) {
                const int r = m0 + warp_m * 32 + mi * 16 + er;
                const int c = n0 + warp_n * 32 + ni * 8 + ec;
                uint32_t h, l;
                split2h(acc[mi][ni][0], acc[mi][ni][1], h, l);
                *(uint32_t*)(Qh + (size_t)r * N + c) = h;
                *(uint32_t*)(Ql + (size_t)r * N + c) = l;
                split2h(acc[mi][ni][2], acc[mi][ni][3], h, l);
                *(uint32_t*)(Qh + (size_t)(r + 8) * N + c) = h;
                *(uint32_t*)(Ql + (size_t)(r + 8) * N + c) = l;
            }
    } else {
        __half* C = (z == 1) ? Kv : Vv;
#pragma unroll
        for (int mi = 0; mi < 2; mi++)
#pragma unroll
            for (int ni = 0; ni < 4; ni++) {
                const int r = m0 + warp_m * 32 + mi * 16 + er;
                const int c = n0 + warp_n * 32 + ni * 8 + ec;
                *(uint32_t*)(C + (size_t)r * N + c) =
                    packh(acc[mi][ni][0], acc[mi][ni][1]);
                *(uint32_t*)(C + (size_t)(r + 8) * N + c) =
                    packh(acc[mi][ni][2], acc[mi][ni][3]);
            }
    }
}

// ===========================================================================
// gemm_out: out = X @ Wo^T. X fp16 split pair (copied), Wo f32 (converted).
// ===========================================================================
__global__ __launch_bounds__(512, 1)
void gemm_out(const __half* __restrict__ Xh, const __half* __restrict__ Xl,
              const float* __restrict__ Wo, float* __restrict__ out)
{
    extern __shared__ char smc[];
    const uint32_t sb = smem_u32(smc);
    const int tid  = threadIdx.x;
    const int wid  = tid >> 5;
    const int lane = tid & 31;
    const int warp_m = wid & 3;
    const int warp_n = wid >> 2;
    const int m0 = blockIdx.y * 128;
    const int n0 = blockIdx.x * 128;
    const int K  = D_DIM, N = D_DIM;

    const __half* Ahb = Xh + (size_t)m0 * K;
    const __half* Alb = Xl + (size_t)m0 * K;
    const float*  Wb  = Wo + (size_t)n0 * K;

    float acc[2][4][4];
#pragma unroll
    for (int mi = 0; mi < 2; mi++)
#pragma unroll
        for (int ni = 0; ni < 4; ni++)
#pragma unroll
            for (int q = 0; q < 4; q++) acc[mi][ni][q] = 0.f;

    const int lr  = lane & 15;
    const int lkb = (lane >> 4) << 4;

    uint4 ph[2], pl[2];
    float4 pw[4];
    auto load_regs = [&](int s) {
#pragma unroll
        for (int i = 0; i < 2; i++) {
            const int c = i * 512 + tid;          // 0..1023
            const int row = c >> 3, ch = c & 7;
            ph[i] = *(const uint4*)(Ahb + (size_t)row * K + s * 64 + ch * 8);
            pl[i] = *(const uint4*)(Alb + (size_t)row * K + s * 64 + ch * 8);
        }
#pragma unroll
        for (int i = 0; i < 4; i++) {
            const int c = i * 512 + tid;
            const int row = c >> 4, ch = c & 15;
            pw[i] = *(const float4*)(Wb + (size_t)row * K + s * 64 + ch * 4);
        }
    };
    auto store_regs = [&](uint32_t bufo) {
        char* hi_p = smc + bufo;
        char* lo_p = smc + bufo + GT;
        char* b_p  = smc + bufo + 2 * GT;
#pragma unroll
        for (int i = 0; i < 2; i++) {
            const int c = i * 512 + tid;
            const int row = c >> 3, ch = c & 7;
            const uint32_t off = row * SASB + ch * 16;
            *(uint4*)(hi_p + off) = ph[i];
            *(uint4*)(lo_p + off) = pl[i];
        }
#pragma unroll
        for (int i = 0; i < 4; i++) {
            const int c = i * 512 + tid;
            const int row = c >> 4, ch = c & 15;
            *(uint2*)(b_p + row * SASB + ch * 8) =
                make_uint2(packh(pw[i].x, pw[i].y), packh(pw[i].z, pw[i].w));
        }
    };

    load_regs(0);
    store_regs(0);
    __syncthreads();

    for (int s = 0; s < STAGES; s++) {
        if (s + 1 < STAGES) load_regs(s + 1);
        gemm_stage_compute(sb + (s & 1) * GSTAGE, warp_m, warp_n, lr, lkb, acc);
        if (s + 1 < STAGES) store_regs(((s + 1) & 1) * GSTAGE);
        __syncthreads();
    }

    const int er = lane >> 2;
    const int ec = (lane & 3) * 2;
#pragma unroll
    for (int mi = 0; mi < 2; mi++)
#pragma unroll
        for (int ni = 0; ni < 4; ni++) {
            const int r = m0 + warp_m * 32 + mi * 16 + er;
            const int c = n0 + warp_n * 32 + ni * 8 + ec;
            *(float2*)(out + (size_t)r * N + c) =
                make_float2(acc[mi][ni][0], acc[mi][ni][1]);
            *(float2*)(out + (size_t)(r + 8) * N + c) =
                make_float2(acc[mi][ni][2], acc[mi][ni][3]);
        }
}

// ===========================================================================
// Flash attention (causal). CTA = 256 q-rows x (b,h), 512 threads (16 warps,
// warp w owns q-rows [w*16, w*16+16)). K/V 64-row blocks, double-buffered.
// ===========================================================================
constexpr int FQT  = 256 * SASB;           // 36864 per 256-row Q tile
constexpr int FQHI = 0;
constexpr int FQLO = FQHI + FQT;           // 36864
constexpr int FKV0 = FQLO + FQT;           // 73728
constexpr int KVT  = 64 * SASB;            // 9216 per 64-row tile
constexpr int KVBUF = 2 * KVT;             // 18432 (K, V)
constexpr int FSM_TOTAL = FKV0 + 2 * KVBUF;  // 110592

__global__ __launch_bounds__(512, 1)
void flash_mma(const __half* __restrict__ Qh, const __half* __restrict__ Ql,
               const __half* __restrict__ Kv, const __half* __restrict__ Vv,
               __half* __restrict__ Xh, __half* __restrict__ Xl)
{
    extern __shared__ char smc[];
    const uint32_t sb = smem_u32(smc);
    const int tid  = threadIdx.x;
    const int wid  = tid >> 5;
    const int lane = tid & 31;
    const int qb   = gridDim.x - 1 - blockIdx.x;   // longest blocks first
    const int h    = blockIdx.y;
    const int b    = blockIdx.z;

    const size_t head = (size_t)b * S_LEN * D_DIM + (size_t)h * DKH;
    const int prow = tid >> 3;    // 0..63
    const int pch  = tid & 7;

    // ---- Q tiles (hi, lo): 256 rows, 8 cp.async per thread ----
    {
        const __half* qb_[2] = {Qh + head, Ql + head};
#pragma unroll
        for (int i = 0; i < 8; i++) {
            const int t   = i >> 2;
            const int row = ((i & 3) << 6) | prow;      // 0..255
            const void* src = qb_[t] + (size_t)(qb * 256 + row) * D_DIM + pch * 8;
            cpasync16(sb + t * FQT + row * SASB + pch * 16, src);
        }
    }

    const __half* kvb[2] = {Kv + head, Vv + head};
    auto produce_kv = [&](int kb) {
        const uint32_t bufb = sb + FKV0 + (kb & 1) * KVBUF;
#pragma unroll
        for (int i = 0; i < 2; i++) {
            const void* src = kvb[i] + (size_t)(kb * 64 + prow) * D_DIM + pch * 8;
            cpasync16(bufb + i * KVT + prow * SASB + pch * 16, src);
        }
    };

    produce_kv(0);
    cp_commit();

    float o[8][4];
    float m0r = -1e30f, m1r = -1e30f, l0r = 0.f, l1r = 0.f;
#pragma unroll
    for (int ni = 0; ni < 8; ni++)
#pragma unroll
        for (int q = 0; q < 4; q++) o[ni][q] = 0.f;

    const int lr  = lane & 15;
    const int lkb = (lane >> 4) << 4;
    const int kb_max = 4 * qb + 3;

    for (int kb = 0; kb <= kb_max; kb++) {
        if (kb < kb_max) {
            produce_kv(kb + 1);
            cp_commit();
            cp_wait1();
        } else {
            cp_wait0();
        }
        __syncthreads();

        const uint32_t kvbase = sb + FKV0 + (kb & 1) * KVBUF;

        // ---- QK^T ----
        float sc[8][4];
#pragma unroll
        for (int ni = 0; ni < 8; ni++)
#pragma unroll
            for (int q = 0; q < 4; q++) sc[ni][q] = 0.f;

#pragma unroll
        for (int ks = 0; ks < 4; ks++) {
            const uint32_t abyte = (wid * 16 + lr) * SASB + ks * 32 + lkb;
            uint32_t qh[4], ql[4];
            ldmx4(qh, sb + FQHI + abyte);
            ldmx4(ql, sb + FQLO + abyte);
#pragma unroll
            for (int nb = 0; nb < 4; nb++) {
                const uint32_t bbyte = (nb * 16 + lr) * SASB + ks * 32 + lkb;
                uint32_t kh[4];
                ldmx4(kh, kvbase + bbyte);
                mma16816(sc[nb * 2],     qh, kh[0], kh[2]);
                mma16816(sc[nb * 2],     ql, kh[0], kh[2]);
                mma16816(sc[nb * 2 + 1], qh, kh[1], kh[3]);
                mma16816(sc[nb * 2 + 1], ql, kh[1], kh[3]);
            }
        }

#pragma unroll
        for (int ni = 0; ni < 8; ni++)
#pragma unroll
            for (int q = 0; q < 4; q++) sc[ni][q] *= 0.125f;

        // ---- causal mask ----
        const int q0 = qb * 256 + wid * 16 + (lane >> 2);
        if (kb * 64 + 63 > qb * 256 + wid * 16) {
#pragma unroll
            for (int ni = 0; ni < 8; ni++) {
#pragma unroll
                for (int c = 0; c < 2; c++) {
                    const int col = kb * 64 + ni * 8 + (lane & 3) * 2 + c;
                    if (col > q0)     sc[ni][c]     = -1e30f;
                    if (col > q0 + 8) sc[ni][2 + c] = -1e30f;
                }
            }
        }

        // ---- online softmax ----
        float mx0 = -1e30f, mx1 = -1e30f;
#pragma unroll
        for (int ni = 0; ni < 8; ni++) {
            mx0 = fmaxf(mx0, fmaxf(sc[ni][0], sc[ni][1]));
            mx1 = fmaxf(mx1, fmaxf(sc[ni][2], sc[ni][3]));
        }
        mx0 = fmaxf(mx0, __shfl_xor_sync(0xffffffffu, mx0, 1));
        mx0 = fmaxf(mx0, __shfl_xor_sync(0xffffffffu, mx0, 2));
        mx1 = fmaxf(mx1, __shfl_xor_sync(0xffffffffu, mx1, 1));
        mx1 = fmaxf(mx1, __shfl_xor_sync(0xffffffffu, mx1, 2));

        const float mn0 = fmaxf(m0r, mx0);
        const float mn1 = fmaxf(m1r, mx1);
        const float al0 = __expf(m0r - mn0);
        const float al1 = __expf(m1r - mn1);
        m0r = mn0; m1r = mn1;

        float ls0 = 0.f, ls1 = 0.f;
#pragma unroll
        for (int ni = 0; ni < 8; ni++) {
            sc[ni][0] = __expf(sc[ni][0] - mn0); ls0 += sc[ni][0];
            sc[ni][1] = __expf(sc[ni][1] - mn0); ls0 += sc[ni][1];
            sc[ni][2] = __expf(sc[ni][2] - mn1); ls1 += sc[ni][2];
            sc[ni][3] = __expf(sc[ni][3] - mn1); ls1 += sc[ni][3];
        }
        ls0 += __shfl_xor_sync(0xffffffffu, ls0, 1);
        ls0 += __shfl_xor_sync(0xffffffffu, ls0, 2);
        ls1 += __shfl_xor_sync(0xffffffffu, ls1, 1);
        ls1 += __shfl_xor_sync(0xffffffffu, ls1, 2);
        l0r = l0r * al0 + ls0;
        l1r = l1r * al1 + ls1;
#pragma unroll
        for (int ni = 0; ni < 8; ni++) {
            o[ni][0] *= al0; o[ni][1] *= al0;
            o[ni][2] *= al1; o[ni][3] *= al1;
        }

        // ---- P.V ----
#pragma unroll
        for (int ks = 0; ks < 4; ks++) {
            uint32_t ph[4], pl[4];
            split2h(sc[2 * ks][0],     sc[2 * ks][1],     ph[0], pl[0]);
            split2h(sc[2 * ks][2],     sc[2 * ks][3],     ph[1], pl[1]);
            split2h(sc[2 * ks + 1][0], sc[2 * ks + 1][1], ph[2], pl[2]);
            split2h(sc[2 * ks + 1][2], sc[2 * ks + 1][3], ph[3], pl[3]);
#pragma unroll
            for (int nt = 0; nt < 4; nt++) {
                const uint32_t vbyte =
                    (ks * 16 + ((lane >> 3) & 1) * 8 + (lane & 7)) * SASB +
                    nt * 32 + ((lane >> 4) << 4);
                uint32_t vh[4];
                ldmx4t(vh, kvbase + KVT + vbyte);
                mma16816(o[nt * 2],     ph, vh[0], vh[1]);
                mma16816(o[nt * 2],     pl, vh[0], vh[1]);
                mma16816(o[nt * 2 + 1], ph, vh[2], vh[3]);
                mma16816(o[nt * 2 + 1], pl, vh[2], vh[3]);
            }
        }
        __syncthreads();
    }

    // ---- epilogue: split fp16 write ----
    const float inv0 = 1.f / l0r;
    const float inv1 = 1.f / l1r;
    const int r0 = qb * 256 + wid * 16 + (lane >> 2);
    const int ec = (lane & 3) * 2;
#pragma unroll
    for (int ni = 0; ni < 8; ni++) {
        const size_t c = head + (size_t)ni * 8 + ec;
        uint32_t hh, ll;
        split2h(o[ni][0] * inv0, o[ni][1] * inv0, hh, ll);
        *(uint32_t*)(Xh + c + (size_t)r0 * D_DIM) = hh;
        *(uint32_t*)(Xl + c + (size_t)r0 * D_DIM) = ll;
        split2h(o[ni][2] * inv1, o[ni][3] * inv1, hh, ll);
        *(uint32_t*)(Xh + c + (size_t)(r0 + 8) * D_DIM) = hh;
        *(uint32_t*)(Xl + c + (size_t)(r0 + 8) * D_DIM) = ll;
    }
}

// ---------------------------------------------------------------------------
// launch
// ---------------------------------------------------------------------------
extern "C" void kernel_launch(void* const* d_in, const int* in_sizes, int n_in,
                              void* d_out, int out_size)
{
    const float* query = (const float*)d_in[0];
    const float* key   = (const float*)d_in[1];
    const float* value = (const float*)d_in[2];
    const float* Wq    = (const float*)d_in[3];
    const float* Wk    = (const float*)d_in[4];
    const float* Wv    = (const float*)d_in[5];
    const float* Wo    = (const float*)d_in[6];
    float* out = (float*)d_out;

    __half *Qh, *Ql, *Kv, *Vv, *Xh, *Xl;
    cudaGetSymbolAddress((void**)&Qh, g_Qh); cudaGetSymbolAddress((void**)&Ql, g_Ql);
    cudaGetSymbolAddress((void**)&Kv, g_Kv); cudaGetSymbolAddress((void**)&Vv, g_Vv);
    cudaGetSymbolAddress((void**)&Xh, g_Xh); cudaGetSymbolAddress((void**)&Xl, g_Xl);

    cudaFuncSetAttribute(gemm_proj, cudaFuncAttributeMaxDynamicSharedMemorySize,
                         SM_GEMM_TOTAL);
    cudaFuncSetAttribute(gemm_out, cudaFuncAttributeMaxDynamicSharedMemorySize,
                         SM_GEMM_TOTAL);
    cudaFuncSetAttribute(flash_mma, cudaFuncAttributeMaxDynamicSharedMemorySize,
                         FSM_TOTAL);

    dim3 pgrid(D_DIM / 128, MTOT / 128, 3);   // (8, 32, 3)
    gemm_proj<<<pgrid, 512, SM_GEMM_TOTAL>>>(query, key, value, Wq, Wk, Wv,
                                             Qh, Ql, Kv, Vv);

    dim3 fgrid(S_LEN / 256, H_NUM, B_SZ);     // (8, 16, 2)
    flash_mma<<<fgrid, 512, FSM_TOTAL>>>(Qh, Ql, Kv, Vv, Xh, Xl);

    dim3 ogrid(D_DIM / 128, MTOT / 128);      // (8, 32)
    gemm_out<<<ogrid, 512, SM_GEMM_TOTAL>>>(Xh, Xl, Wo, out);
}